// round 11
// baseline (speedup 1.0000x reference)
#include <cuda_runtime.h>

#define Nn   60000
#define M1n  40000
#define M2n  40000
#define GB   592     // k_pre blocks: 254 (h0) + 169 (h1) + 169 (h2) = 4/SM
#define PB0  254
#define PB1  169
#define KB2  296     // blocks for k_beta (2 per SM x 148 = one resident wave)

// ------------------------- device scratch (no allocs allowed) ---------------
__device__ __align__(16) float g_e0[(size_t)Nn * 64];
__device__ __align__(16) float g_e1[(size_t)Nn * 64];
__device__ __align__(16) float g_t0[M1n];
__device__ __align__(16) float g_t1[M2n];
__device__ __align__(16) float g_r0[Nn];
__device__ __align__(16) float g_r1[Nn];
__device__ __align__(16) float g_gs[GB];
__device__ __align__(16) float g_gv[GB * 64];
__device__ __align__(16) float g_bpart[KB2 * 2];
__device__ int   g_ctr;                     // zero-init; self-resets each run
__device__ int   g_flag;                    // beta-ready release flag (self-resets)
__device__ int   g_ctr2;                    // out-phase completion counter
__device__ __align__(16) float g_fin[68];   // [0..63] global_embed, [64] b0, [65] b1

// ------------------------- helpers ------------------------------------------
typedef unsigned long long u64;

__device__ __forceinline__ u64 ffma2(u64 a, u64 b, u64 c) {
    u64 d;
    asm("fma.rn.f32x2 %0, %1, %2, %3;" : "=l"(d) : "l"(a), "l"(b), "l"(c));
    return d;
}
__device__ __forceinline__ float f2lo(u64 v) { return __uint_as_float((unsigned int)v); }
__device__ __forceinline__ float f2hi(u64 v) { return __uint_as_float((unsigned int)(v >> 32)); }
__device__ __forceinline__ u64 d2u(double d) { return (u64)__double_as_longlong(d); }
__device__ __forceinline__ float tanh_fast(float x) {
    float y;
    asm("tanh.approx.f32 %0, %1;" : "=f"(y) : "f"(x));
    return y;
}
__device__ __forceinline__ float dot4(float4 a, float4 b) {
    return a.x * b.x + a.y * b.y + a.z * b.z + a.w * b.w;
}

// ------------------------- k_pre --------------------------------------------
// Region-partitioned blocks (uniform mode per block), half-warp per row,
// 2 rows per iteration for MLP. Global-pool partials: sum(exp), sum(exp*row).
__global__ __launch_bounds__(256) void k_pre(
    const float* __restrict__ h0, const float* __restrict__ h1,
    const float* __restrict__ h2, const float* __restrict__ aw0,
    const float* __restrict__ aw1, const float* __restrict__ glob)
{
    const int lane = threadIdx.x & 31;
    const int wid  = threadIdx.x >> 5;
    const int half = lane >> 4;
    const int l    = lane & 15;
    const int hw   = wid * 2 + half;               // half-warp id in block (0..15)

    const int b = blockIdx.x;
    const float* base;
    int nrows, bb, mode;
    if (b < PB0)            { base = h0; nrows = Nn;  bb = b;             mode = 0; }
    else if (b < PB0 + PB1) { base = h1; nrows = M1n; bb = b - PB0;       mode = 1; }
    else                    { base = h2; nrows = M2n; bb = b - PB0 - PB1; mode = 2; }
    const int NHW = ((mode == 0) ? PB0 : PB1) * 16;
    const int ghw = bb * 16 + hw;

    float4 gl  = ((const float4*)glob)[l];
    float4 ar0, ar1, an;
    if (mode == 0) {
        ar0 = ((const float4*)aw0)[l];
        ar1 = ((const float4*)aw1)[l];
    } else if (mode == 1) {
        an = ((const float4*)aw0)[16 + l];
    } else {
        an = ((const float4*)aw1)[16 + l];
    }

    float  sum = 0.f;
    float4 av  = make_float4(0.f, 0.f, 0.f, 0.f);

    for (int i = ghw; i < nrows; i += 2 * NHW) {
        const int i2 = i + NHW;
        const bool has2 = (i2 < nrows);
        float4 v0 = ((const float4*)(base + (size_t)i * 64))[l];
        float4 v1 = has2 ? ((const float4*)(base + (size_t)i2 * 64))[l]
                         : make_float4(0.f, 0.f, 0.f, 0.f);
        float pg0 = dot4(v0, gl);
        float pg1 = dot4(v1, gl);

        if (mode == 0) {
            float d00 = dot4(v0, ar0), d01 = dot4(v0, ar1);
            float d10 = dot4(v1, ar0), d11 = dot4(v1, ar1);
#pragma unroll
            for (int o = 8; o > 0; o >>= 1) {
                pg0 += __shfl_xor_sync(0xffffffffu, pg0, o);
                pg1 += __shfl_xor_sync(0xffffffffu, pg1, o);
                d00 += __shfl_xor_sync(0xffffffffu, d00, o);
                d01 += __shfl_xor_sync(0xffffffffu, d01, o);
                d10 += __shfl_xor_sync(0xffffffffu, d10, o);
                d11 += __shfl_xor_sync(0xffffffffu, d11, o);
            }
            if (l == 0) {
                g_r0[i] = d00; g_r1[i] = d01;
                if (has2) { g_r0[i2] = d10; g_r1[i2] = d11; }
            }
        } else {
            float dt0 = dot4(v0, an);
            float dt1 = dot4(v1, an);
#pragma unroll
            for (int o = 8; o > 0; o >>= 1) {
                pg0 += __shfl_xor_sync(0xffffffffu, pg0, o);
                pg1 += __shfl_xor_sync(0xffffffffu, pg1, o);
                dt0 += __shfl_xor_sync(0xffffffffu, dt0, o);
                dt1 += __shfl_xor_sync(0xffffffffu, dt1, o);
            }
            if (l == 0) {
                float* tp = (mode == 1) ? g_t0 : g_t1;
                tp[i] = dt0;
                if (has2) tp[i2] = dt1;
            }
        }

        float e0 = __expf(pg0 * 0.125f);    // / sqrt(64); scores small, no max needed
        sum  += e0;
        av.x += e0 * v0.x; av.y += e0 * v0.y; av.z += e0 * v0.z; av.w += e0 * v0.w;
        if (has2) {
            float e1 = __expf(pg1 * 0.125f);
            sum  += e1;
            av.x += e1 * v1.x; av.y += e1 * v1.y; av.z += e1 * v1.z; av.w += e1 * v1.w;
        }
    }

    __shared__ float ssum[16];
    __shared__ __align__(16) float svv[16][64];
    if (l == 0) ssum[hw] = sum;
    *(float4*)&svv[hw][4 * l] = av;
    __syncthreads();

    if (threadIdx.x < 64) {
        const int d = threadIdx.x;
        float S = 0.f, V = 0.f;
#pragma unroll
        for (int k = 0; k < 16; k++) { S += ssum[k]; V += svv[k][d]; }
        g_gv[blockIdx.x * 64 + d] = V;
        if (d == 0) g_gs[blockIdx.x] = S;
    }
}

// ------------------------- k_att (half-warp per node) ------------------------
// Softmax-sum reduction DEFERRED until after the gather loop: the gathers only
// need the unnormalized weights (broadcast of p), so row loads start right
// after exp and the 4-stage shfl reduction hides under L2 latency.
template <int S>
__device__ __forceinline__ void att_body(
    int node, int lane, const float* __restrict__ h, const int* __restrict__ nei,
    const float* __restrict__ t, const float* __restrict__ r, float* __restrict__ eo)
{
    const int l = lane & 15;
    constexpr int SA = (S < 16) ? S : 16;
    constexpr int SB = (S > 16) ? S - 16 : 0;

    float rv = __ldg(r + node);
    int   idx_a = 0, idx_b = 0;
    float p_a = 0.f, p_b = 0.f;
    if (l < SA) {
        idx_a = __ldg(nei + node * S + l);
        float sc = rv + __ldg(t + idx_a);
        sc = sc > 0.f ? sc : 0.01f * sc;        // leaky_relu(0.01)
        p_a = __expf(sc);
    }
    if (SB > 0 && l < SB) {
        idx_b = __ldg(nei + node * S + 16 + l);
        float sc = rv + __ldg(t + idx_b);
        sc = sc > 0.f ? sc : 0.01f * sc;
        p_b = __expf(sc);
    }

    float4 acc = make_float4(0.f, 0.f, 0.f, 0.f);
#pragma unroll
    for (int s = 0; s < SA; s++) {
        int   bi = __shfl_sync(0xffffffffu, idx_a, s, 16);
        float wb = __shfl_sync(0xffffffffu, p_a,  s, 16);
        float4 v = *(const float4*)(h + (size_t)bi * 64 + 4 * l);
        acc.x += wb * v.x; acc.y += wb * v.y;
        acc.z += wb * v.z; acc.w += wb * v.w;
    }
#pragma unroll
    for (int s = 0; s < SB; s++) {
        int   bi = __shfl_sync(0xffffffffu, idx_b, s, 16);
        float wb = __shfl_sync(0xffffffffu, p_b,  s, 16);
        float4 v = *(const float4*)(h + (size_t)bi * 64 + 4 * l);
        acc.x += wb * v.x; acc.y += wb * v.y;
        acc.z += wb * v.z; acc.w += wb * v.w;
    }

    // deferred normalizer reduction
    float e = p_a + p_b;
#pragma unroll
    for (int o = 8; o > 0; o >>= 1) e += __shfl_xor_sync(0xffffffffu, e, o);
    float inv = 1.f / e;

    acc.x *= inv; acc.y *= inv; acc.z *= inv; acc.w *= inv;
    acc.x = acc.x > 0.f ? acc.x : __expf(acc.x) - 1.f;   // ELU
    acc.y = acc.y > 0.f ? acc.y : __expf(acc.y) - 1.f;
    acc.z = acc.z > 0.f ? acc.z : __expf(acc.z) - 1.f;
    acc.w = acc.w > 0.f ? acc.w : __expf(acc.w) - 1.f;
    ((float4*)eo)[(size_t)node * 16 + l] = acc;
}

__global__ __launch_bounds__(256) void k_att2(
    const float* __restrict__ h1, const float* __restrict__ h2,
    const int* __restrict__ nei0, const int* __restrict__ nei1)
{
    const int HALFG = Nn / 16;             // 3750 blocks per branch (16 nodes/block)
    const int lane  = threadIdx.x & 31;
    if (blockIdx.x < HALFG) {
        const int node = ((blockIdx.x * 256 + threadIdx.x) >> 5) * 2 + (lane >> 4);
        att_body<20>(node, lane, h2, nei1, g_t1, g_r1, g_e1);
    } else {
        const int node = (((blockIdx.x - HALFG) * 256 + threadIdx.x) >> 5) * 2 + (lane >> 4);
        att_body<10>(node, lane, h1, nei0, g_t0, g_r0, g_e0);
    }
}

// ------------------------- k_beta3 (+combine +fused out) ---------------------
// Phase A: lane=node beta partials (fcW broadcast from SMEM).
// Phase B: last-arriving block combines beta + global pooling, releases g_flag.
// Phase C: all blocks (exactly one resident wave at 2 blocks/SM -> spin is
// deadlock-free) write the final output. Spin uses VOLATILE READS (not atomics)
// so 296 pollers don't serialize on the L2 atomic ALU. Flags self-reset.
__global__ __launch_bounds__(256, 2) void k_beta3(
    const float* __restrict__ fcw, const float* __restrict__ fcb,
    const float* __restrict__ fus, const float* __restrict__ gate,
    float* __restrict__ out)
{
    __shared__ __align__(16) double2 wsh[1024];
    __shared__ float bsh[64], fsh[64];
    __shared__ float r0s[256], r1s[256];

    const int tid  = threadIdx.x;
    const int lane = tid & 31;
    const double2* fw = (const double2*)fcw;
    for (int i = tid; i < 1024; i += 256) wsh[i] = fw[i];
    if (tid < 64) { bsh[tid] = fcb[tid]; fsh[tid] = fus[tid]; }
    __syncthreads();

    float acc0 = 0.f, acc1 = 0.f;
    {
        const int wg = (blockIdx.x * 256 + tid) >> 5;
        const int NW = KB2 * 8;
        const int NC = (2 * Nn) / 32;

        for (int c = wg; c < NC; c += NW) {
            const int phase = (c >= NC / 2);
            const float* src = phase ? g_e1 : g_e0;
            const int node = (phase ? (c - NC / 2) : c) * 32 + lane;
            const double2* e2 = (const double2*)(src + (size_t)node * 64);
            u64 ed[32];
#pragma unroll
            for (int i = 0; i < 16; i++) {
                double2 v = e2[i];
                ed[2 * i]     = d2u(v.x);
                ed[2 * i + 1] = d2u(v.y);
            }

            float accp = 0.f;
#pragma unroll 2
            for (int j = 0; j < 64; j += 2) {
                const double2* wj = wsh + j * 16;
                u64 a0 = 0ull, a1 = 0ull, b0 = 0ull, b1 = 0ull;
#pragma unroll
                for (int i = 0; i < 16; i += 2) {
                    double2 w0  = wj[i];
                    double2 w0b = wj[i + 1];
                    double2 w1  = wj[16 + i];
                    double2 w1b = wj[16 + i + 1];
                    a0 = ffma2(d2u(w0.x),  ed[2 * i],     a0);
                    a1 = ffma2(d2u(w0.y),  ed[2 * i + 1], a1);
                    a0 = ffma2(d2u(w0b.x), ed[2 * i + 2], a0);
                    a1 = ffma2(d2u(w0b.y), ed[2 * i + 3], a1);
                    b0 = ffma2(d2u(w1.x),  ed[2 * i],     b0);
                    b1 = ffma2(d2u(w1.y),  ed[2 * i + 1], b1);
                    b0 = ffma2(d2u(w1b.x), ed[2 * i + 2], b0);
                    b1 = ffma2(d2u(w1b.y), ed[2 * i + 3], b1);
                }
                float d0 = ((f2lo(a0) + f2hi(a0)) + (f2lo(a1) + f2hi(a1))) + bsh[j];
                float d1 = ((f2lo(b0) + f2hi(b0)) + (f2lo(b1) + f2hi(b1))) + bsh[j + 1];
                accp += fsh[j] * tanh_fast(d0) + fsh[j + 1] * tanh_fast(d1);
            }
            if (phase) acc1 += accp; else acc0 += accp;
        }
    }

    r0s[tid] = acc0;
    r1s[tid] = acc1;
    __syncthreads();
    for (int off = 128; off > 0; off >>= 1) {
        if (tid < off) { r0s[tid] += r0s[tid + off]; r1s[tid] += r1s[tid + off]; }
        __syncthreads();
    }

    __shared__ int lastFlag;
    if (tid == 0) {
        g_bpart[blockIdx.x * 2]     = r0s[0];
        g_bpart[blockIdx.x * 2 + 1] = r1s[0];
        __threadfence();
        lastFlag = (atomicAdd(&g_ctr, 1) == KB2 - 1);
    }
    __syncthreads();

    if (lastFlag) {
        __threadfence();
        // global pooling combine (plain sums)
        if (tid < 64) {
            float S = 0.f, V = 0.f;
            for (int b = 0; b < GB; b++) {
                S += g_gs[b];
                V += g_gv[b * 64 + tid];
            }
            g_fin[tid] = V / S;
        }
        float p0 = 0.f, p1 = 0.f;
        for (int i = tid; i < KB2; i += 256) { p0 += g_bpart[2 * i]; p1 += g_bpart[2 * i + 1]; }
        r0s[tid] = p0; r1s[tid] = p1;
        __syncthreads();
        for (int off = 128; off > 0; off >>= 1) {
            if (tid < off) { r0s[tid] += r0s[tid + off]; r1s[tid] += r1s[tid + off]; }
            __syncthreads();
        }
        if (tid == 0) {
            float m0 = r0s[0] / (float)Nn, m1 = r1s[0] / (float)Nn;
            float mm = fmaxf(m0, m1);
            float e0 = __expf(m0 - mm), e1 = __expf(m1 - mm);
            float is = 1.f / (e0 + e1);
            g_fin[64] = e0 * is;
            g_fin[65] = e1 * is;
            g_ctr = 0;                       // reset partial counter
            __threadfence();
            *((volatile int*)&g_flag) = 1;   // release all blocks
        }
    }

    // ---- Phase C: wait for beta (volatile read spin), write output slice ----
    if (tid == 0) {
        while (*((volatile int*)&g_flag) == 0) { __nanosleep(64); }
    }
    __syncthreads();
    __threadfence();

    {
        float gv = 1.f / (1.f + __expf(-gate[0]));
        float b0 = gv * g_fin[64], b1 = gv * g_fin[65], cg = 1.f - gv;
        const int TOT = Nn * 16;   // float4 count
        const int beg = (int)(((long long)blockIdx.x * TOT) / KB2);
        const int end = (int)(((long long)(blockIdx.x + 1) * TOT) / KB2);
        for (int i = beg + tid; i < end; i += 256) {
            float4 a  = ((const float4*)g_e0)[i];
            float4 b  = ((const float4*)g_e1)[i];
            float4 ge = ((const float4*)g_fin)[i & 15];
            float4 o;
            o.x = b0 * a.x + b1 * b.x + cg * ge.x;
            o.y = b0 * a.y + b1 * b.y + cg * ge.y;
            o.z = b0 * a.z + b1 * b.z + cg * ge.z;
            o.w = b0 * a.w + b1 * b.w + cg * ge.w;
            ((float4*)out)[i] = o;
        }
    }

    // reset g_flag after every block finished its out slice (all passed spin)
    __syncthreads();
    if (tid == 0) {
        if (atomicAdd(&g_ctr2, 1) == KB2 - 1) {
            g_ctr2 = 0;
            __threadfence();
            *((volatile int*)&g_flag) = 0;
        }
    }
}

// ------------------------- launch -------------------------------------------
extern "C" void kernel_launch(void* const* d_in, const int* in_sizes, int n_in,
                              void* d_out, int out_size)
{
    const float* h0   = (const float*)d_in[0];
    const float* h1   = (const float*)d_in[1];
    const float* h2   = (const float*)d_in[2];
    const int*   nei0 = (const int*)d_in[3];
    const int*   nei1 = (const int*)d_in[4];
    const float* aw0  = (const float*)d_in[5];
    const float* aw1  = (const float*)d_in[6];
    const float* fcw  = (const float*)d_in[7];
    const float* fcb  = (const float*)d_in[8];
    const float* fus  = (const float*)d_in[9];
    const float* glob = (const float*)d_in[10];
    const float* gate = (const float*)d_in[11];
    float* out = (float*)d_out;
    (void)in_sizes; (void)n_in; (void)out_size;

    k_pre<<<GB, 256>>>(h0, h1, h2, aw0, aw1, glob);
    k_att2<<<2 * (Nn / 16), 256>>>(h1, h2, nei0, nei1);
    k_beta3<<<KB2, 256>>>(fcw, fcb, fus, gate, out);
}

// round 14
// speedup vs baseline: 1.0433x; 1.0433x over previous
#include <cuda_runtime.h>

#define Nn   60000
#define M1n  40000
#define M2n  40000
#define GB   592     // k_pre blocks: 254 (h0) + 169 (h1) + 169 (h2) = 4/SM
#define PB0  254
#define PB1  169
#define KB2  296     // blocks for k_beta (2 per SM x 148)

// ------------------------- device scratch (no allocs allowed) ---------------
__device__ __align__(16) float g_e0[(size_t)Nn * 64];
__device__ __align__(16) float g_e1[(size_t)Nn * 64];
__device__ __align__(16) float g_t0[M1n];
__device__ __align__(16) float g_t1[M2n];
__device__ __align__(16) float g_r0[Nn];
__device__ __align__(16) float g_r1[Nn];
__device__ __align__(16) float g_gs[GB];
__device__ __align__(16) float g_gv[GB * 64];
__device__ __align__(16) float g_bpart[KB2 * 2];
__device__ int   g_ctr;                     // zero-init; self-resets each run
__device__ __align__(16) float g_fin[68];   // [0..63] global_embed, [64] b0, [65] b1

// ------------------------- helpers ------------------------------------------
typedef unsigned long long u64;

__device__ __forceinline__ u64 ffma2(u64 a, u64 b, u64 c) {
    u64 d;
    asm("fma.rn.f32x2 %0, %1, %2, %3;" : "=l"(d) : "l"(a), "l"(b), "l"(c));
    return d;
}
__device__ __forceinline__ float f2lo(u64 v) { return __uint_as_float((unsigned int)v); }
__device__ __forceinline__ float f2hi(u64 v) { return __uint_as_float((unsigned int)(v >> 32)); }
__device__ __forceinline__ u64 d2u(double d) { return (u64)__double_as_longlong(d); }
__device__ __forceinline__ float tanh_fast(float x) {
    float y;
    asm("tanh.approx.f32 %0, %1;" : "=f"(y) : "f"(x));
    return y;
}
__device__ __forceinline__ float dot4(float4 a, float4 b) {
    return a.x * b.x + a.y * b.y + a.z * b.z + a.w * b.w;
}

// ------------------------- k_pre --------------------------------------------
// Region-partitioned blocks (uniform mode per block), half-warp per row,
// 2 rows per iteration for MLP. Global-pool partials: sum(exp), sum(exp*row).
__global__ __launch_bounds__(256) void k_pre(
    const float* __restrict__ h0, const float* __restrict__ h1,
    const float* __restrict__ h2, const float* __restrict__ aw0,
    const float* __restrict__ aw1, const float* __restrict__ glob)
{
    const int lane = threadIdx.x & 31;
    const int wid  = threadIdx.x >> 5;
    const int half = lane >> 4;
    const int l    = lane & 15;
    const int hw   = wid * 2 + half;               // half-warp id in block (0..15)

    const int b = blockIdx.x;
    const float* base;
    int nrows, bb, mode;
    if (b < PB0)            { base = h0; nrows = Nn;  bb = b;             mode = 0; }
    else if (b < PB0 + PB1) { base = h1; nrows = M1n; bb = b - PB0;       mode = 1; }
    else                    { base = h2; nrows = M2n; bb = b - PB0 - PB1; mode = 2; }
    const int NHW = ((mode == 0) ? PB0 : PB1) * 16;
    const int ghw = bb * 16 + hw;

    float4 gl  = ((const float4*)glob)[l];
    float4 ar0, ar1, an;
    if (mode == 0) {
        ar0 = ((const float4*)aw0)[l];
        ar1 = ((const float4*)aw1)[l];
    } else if (mode == 1) {
        an = ((const float4*)aw0)[16 + l];
    } else {
        an = ((const float4*)aw1)[16 + l];
    }

    float  sum = 0.f;
    float4 av  = make_float4(0.f, 0.f, 0.f, 0.f);

    for (int i = ghw; i < nrows; i += 2 * NHW) {
        const int i2 = i + NHW;
        const bool has2 = (i2 < nrows);
        float4 v0 = ((const float4*)(base + (size_t)i * 64))[l];
        float4 v1 = has2 ? ((const float4*)(base + (size_t)i2 * 64))[l]
                         : make_float4(0.f, 0.f, 0.f, 0.f);
        float pg0 = dot4(v0, gl);
        float pg1 = dot4(v1, gl);

        if (mode == 0) {
            float d00 = dot4(v0, ar0), d01 = dot4(v0, ar1);
            float d10 = dot4(v1, ar0), d11 = dot4(v1, ar1);
#pragma unroll
            for (int o = 8; o > 0; o >>= 1) {
                pg0 += __shfl_xor_sync(0xffffffffu, pg0, o);
                pg1 += __shfl_xor_sync(0xffffffffu, pg1, o);
                d00 += __shfl_xor_sync(0xffffffffu, d00, o);
                d01 += __shfl_xor_sync(0xffffffffu, d01, o);
                d10 += __shfl_xor_sync(0xffffffffu, d10, o);
                d11 += __shfl_xor_sync(0xffffffffu, d11, o);
            }
            if (l == 0) {
                g_r0[i] = d00; g_r1[i] = d01;
                if (has2) { g_r0[i2] = d10; g_r1[i2] = d11; }
            }
        } else {
            float dt0 = dot4(v0, an);
            float dt1 = dot4(v1, an);
#pragma unroll
            for (int o = 8; o > 0; o >>= 1) {
                pg0 += __shfl_xor_sync(0xffffffffu, pg0, o);
                pg1 += __shfl_xor_sync(0xffffffffu, pg1, o);
                dt0 += __shfl_xor_sync(0xffffffffu, dt0, o);
                dt1 += __shfl_xor_sync(0xffffffffu, dt1, o);
            }
            if (l == 0) {
                float* tp = (mode == 1) ? g_t0 : g_t1;
                tp[i] = dt0;
                if (has2) tp[i2] = dt1;
            }
        }

        float e0 = __expf(pg0 * 0.125f);    // / sqrt(64); scores small, no max needed
        sum  += e0;
        av.x += e0 * v0.x; av.y += e0 * v0.y; av.z += e0 * v0.z; av.w += e0 * v0.w;
        if (has2) {
            float e1 = __expf(pg1 * 0.125f);
            sum  += e1;
            av.x += e1 * v1.x; av.y += e1 * v1.y; av.z += e1 * v1.z; av.w += e1 * v1.w;
        }
    }

    __shared__ float ssum[16];
    __shared__ __align__(16) float svv[16][64];
    if (l == 0) ssum[hw] = sum;
    *(float4*)&svv[hw][4 * l] = av;
    __syncthreads();

    if (threadIdx.x < 64) {
        const int d = threadIdx.x;
        float S = 0.f, V = 0.f;
#pragma unroll
        for (int k = 0; k < 16; k++) { S += ssum[k]; V += svv[k][d]; }
        g_gv[blockIdx.x * 64 + d] = V;
        if (d == 0) g_gs[blockIdx.x] = S;
    }
}

// ------------------------- k_att (half-warp per node) ------------------------
// Softmax-sum reduction deferred until after the gather loop: gathers only need
// the unnormalized weights, so row loads issue right after exp and the 4-stage
// shfl reduction hides under L2 latency.
template <int S>
__device__ __forceinline__ void att_body(
    int node, int lane, const float* __restrict__ h, const int* __restrict__ nei,
    const float* __restrict__ t, const float* __restrict__ r, float* __restrict__ eo)
{
    const int l = lane & 15;
    constexpr int SA = (S < 16) ? S : 16;
    constexpr int SB = (S > 16) ? S - 16 : 0;

    float rv = __ldg(r + node);
    int   idx_a = 0, idx_b = 0;
    float p_a = 0.f, p_b = 0.f;
    if (l < SA) {
        idx_a = __ldg(nei + node * S + l);
        float sc = rv + __ldg(t + idx_a);
        sc = sc > 0.f ? sc : 0.01f * sc;        // leaky_relu(0.01)
        p_a = __expf(sc);
    }
    if (SB > 0 && l < SB) {
        idx_b = __ldg(nei + node * S + 16 + l);
        float sc = rv + __ldg(t + idx_b);
        sc = sc > 0.f ? sc : 0.01f * sc;
        p_b = __expf(sc);
    }

    float4 acc = make_float4(0.f, 0.f, 0.f, 0.f);
#pragma unroll
    for (int s = 0; s < SA; s++) {
        int   bi = __shfl_sync(0xffffffffu, idx_a, s, 16);
        float wb = __shfl_sync(0xffffffffu, p_a,  s, 16);
        float4 v = *(const float4*)(h + (size_t)bi * 64 + 4 * l);
        acc.x += wb * v.x; acc.y += wb * v.y;
        acc.z += wb * v.z; acc.w += wb * v.w;
    }
#pragma unroll
    for (int s = 0; s < SB; s++) {
        int   bi = __shfl_sync(0xffffffffu, idx_b, s, 16);
        float wb = __shfl_sync(0xffffffffu, p_b,  s, 16);
        float4 v = *(const float4*)(h + (size_t)bi * 64 + 4 * l);
        acc.x += wb * v.x; acc.y += wb * v.y;
        acc.z += wb * v.z; acc.w += wb * v.w;
    }

    // deferred normalizer reduction
    float e = p_a + p_b;
#pragma unroll
    for (int o = 8; o > 0; o >>= 1) e += __shfl_xor_sync(0xffffffffu, e, o);
    float inv = 1.f / e;

    acc.x *= inv; acc.y *= inv; acc.z *= inv; acc.w *= inv;
    acc.x = acc.x > 0.f ? acc.x : __expf(acc.x) - 1.f;   // ELU
    acc.y = acc.y > 0.f ? acc.y : __expf(acc.y) - 1.f;
    acc.z = acc.z > 0.f ? acc.z : __expf(acc.z) - 1.f;
    acc.w = acc.w > 0.f ? acc.w : __expf(acc.w) - 1.f;
    ((float4*)eo)[(size_t)node * 16 + l] = acc;
}

__global__ __launch_bounds__(256) void k_att2(
    const float* __restrict__ h1, const float* __restrict__ h2,
    const int* __restrict__ nei0, const int* __restrict__ nei1)
{
    const int HALFG = Nn / 16;             // 3750 blocks per branch (16 nodes/block)
    const int lane  = threadIdx.x & 31;
    if (blockIdx.x < HALFG) {
        const int node = ((blockIdx.x * 256 + threadIdx.x) >> 5) * 2 + (lane >> 4);
        att_body<20>(node, lane, h2, nei1, g_t1, g_r1, g_e1);
    } else {
        const int node = (((blockIdx.x - HALFG) * 256 + threadIdx.x) >> 5) * 2 + (lane >> 4);
        att_body<10>(node, lane, h1, nei0, g_t0, g_r0, g_e0);
    }
}

// ------------------------- k_beta3 (+fused combine, R10 version) -------------
__global__ __launch_bounds__(256, 2) void k_beta3(
    const float* __restrict__ fcw, const float* __restrict__ fcb,
    const float* __restrict__ fus)
{
    __shared__ __align__(16) double2 wsh[1024];
    __shared__ float bsh[64], fsh[64];
    __shared__ float r0s[256], r1s[256];
    __shared__ int   lastFlag;

    const int tid  = threadIdx.x;
    const int lane = tid & 31;
    const double2* fw = (const double2*)fcw;
    for (int i = tid; i < 1024; i += 256) wsh[i] = fw[i];
    if (tid < 64) { bsh[tid] = fcb[tid]; fsh[tid] = fus[tid]; }
    __syncthreads();

    float acc0 = 0.f, acc1 = 0.f;
    {
        const int wg = (blockIdx.x * 256 + tid) >> 5;
        const int NW = KB2 * 8;
        const int NC = (2 * Nn) / 32;

        for (int c = wg; c < NC; c += NW) {
            const int phase = (c >= NC / 2);
            const float* src = phase ? g_e1 : g_e0;
            const int node = (phase ? (c - NC / 2) : c) * 32 + lane;
            const double2* e2 = (const double2*)(src + (size_t)node * 64);
            u64 ed[32];
#pragma unroll
            for (int i = 0; i < 16; i++) {
                double2 v = e2[i];
                ed[2 * i]     = d2u(v.x);
                ed[2 * i + 1] = d2u(v.y);
            }

            float accp = 0.f;
#pragma unroll 2
            for (int j = 0; j < 64; j += 2) {
                const double2* wj = wsh + j * 16;
                u64 a0 = 0ull, a1 = 0ull, b0 = 0ull, b1 = 0ull;
#pragma unroll
                for (int i = 0; i < 16; i += 2) {
                    double2 w0  = wj[i];
                    double2 w0b = wj[i + 1];
                    double2 w1  = wj[16 + i];
                    double2 w1b = wj[16 + i + 1];
                    a0 = ffma2(d2u(w0.x),  ed[2 * i],     a0);
                    a1 = ffma2(d2u(w0.y),  ed[2 * i + 1], a1);
                    a0 = ffma2(d2u(w0b.x), ed[2 * i + 2], a0);
                    a1 = ffma2(d2u(w0b.y), ed[2 * i + 3], a1);
                    b0 = ffma2(d2u(w1.x),  ed[2 * i],     b0);
                    b1 = ffma2(d2u(w1.y),  ed[2 * i + 1], b1);
                    b0 = ffma2(d2u(w1b.x), ed[2 * i + 2], b0);
                    b1 = ffma2(d2u(w1b.y), ed[2 * i + 3], b1);
                }
                float d0 = ((f2lo(a0) + f2hi(a0)) + (f2lo(a1) + f2hi(a1))) + bsh[j];
                float d1 = ((f2lo(b0) + f2hi(b0)) + (f2lo(b1) + f2hi(b1))) + bsh[j + 1];
                accp += fsh[j] * tanh_fast(d0) + fsh[j + 1] * tanh_fast(d1);
            }
            if (phase) acc1 += accp; else acc0 += accp;
        }
    }

    r0s[tid] = acc0;
    r1s[tid] = acc1;
    __syncthreads();
    for (int off = 128; off > 0; off >>= 1) {
        if (tid < off) { r0s[tid] += r0s[tid + off]; r1s[tid] += r1s[tid + off]; }
        __syncthreads();
    }
    if (tid == 0) {
        g_bpart[blockIdx.x * 2]     = r0s[0];
        g_bpart[blockIdx.x * 2 + 1] = r1s[0];
        __threadfence();
        lastFlag = (atomicAdd(&g_ctr, 1) == KB2 - 1);
    }
    __syncthreads();

    if (lastFlag) {
        __threadfence();
        // global pooling combine (plain sums)
        if (tid < 64) {
            float S = 0.f, V = 0.f;
            for (int b = 0; b < GB; b++) {
                S += g_gs[b];
                V += g_gv[b * 64 + tid];
            }
            g_fin[tid] = V / S;
        }
        float p0 = 0.f, p1 = 0.f;
        for (int i = tid; i < KB2; i += 256) { p0 += g_bpart[2 * i]; p1 += g_bpart[2 * i + 1]; }
        r0s[tid] = p0; r1s[tid] = p1;
        __syncthreads();
        for (int off = 128; off > 0; off >>= 1) {
            if (tid < off) { r0s[tid] += r0s[tid + off]; r1s[tid] += r1s[tid + off]; }
            __syncthreads();
        }
        if (tid == 0) {
            float m0 = r0s[0] / (float)Nn, m1 = r1s[0] / (float)Nn;
            float mm = fmaxf(m0, m1);
            float e0 = __expf(m0 - mm), e1 = __expf(m1 - mm);
            float is = 1.f / (e0 + e1);
            g_fin[64] = e0 * is;
            g_fin[65] = e1 * is;
            g_ctr = 0;                  // self-reset for next graph replay
        }
    }
}

// ------------------------- k_out (R10 version) -------------------------------
__global__ __launch_bounds__(256) void k_out(const float* __restrict__ gate,
                                             float* __restrict__ out)
{
    const int tq = blockIdx.x * 256 + threadIdx.x;
    const int Q  = Nn * 8;               // 480000 float4 per slice
    if (tq >= Q) return;
    float gv = 1.f / (1.f + __expf(-gate[0]));
    float b0 = gv * g_fin[64], b1 = gv * g_fin[65], cg = 1.f - gv;
    float4 ge = ((const float4*)g_fin)[tq & 15];   // (k*Q) % 16 == 0
#pragma unroll
    for (int k = 0; k < 2; k++) {
        const int i = tq + k * Q;
        float4 a = ((const float4*)g_e0)[i];
        float4 b = ((const float4*)g_e1)[i];
        float4 o;
        o.x = b0 * a.x + b1 * b.x + cg * ge.x;
        o.y = b0 * a.y + b1 * b.y + cg * ge.y;
        o.z = b0 * a.z + b1 * b.z + cg * ge.z;
        o.w = b0 * a.w + b1 * b.w + cg * ge.w;
        ((float4*)out)[i] = o;
    }
}

// ------------------------- launch -------------------------------------------
extern "C" void kernel_launch(void* const* d_in, const int* in_sizes, int n_in,
                              void* d_out, int out_size)
{
    const float* h0   = (const float*)d_in[0];
    const float* h1   = (const float*)d_in[1];
    const float* h2   = (const float*)d_in[2];
    const int*   nei0 = (const int*)d_in[3];
    const int*   nei1 = (const int*)d_in[4];
    const float* aw0  = (const float*)d_in[5];
    const float* aw1  = (const float*)d_in[6];
    const float* fcw  = (const float*)d_in[7];
    const float* fcb  = (const float*)d_in[8];
    const float* fus  = (const float*)d_in[9];
    const float* glob = (const float*)d_in[10];
    const float* gate = (const float*)d_in[11];
    float* out = (float*)d_out;
    (void)in_sizes; (void)n_in; (void)out_size;

    k_pre<<<GB, 256>>>(h0, h1, h2, aw0, aw1, glob);
    k_att2<<<2 * (Nn / 16), 256>>>(h1, h2, nei0, nei1);
    k_beta3<<<KB2, 256>>>(fcw, fcb, fus);
    k_out<<<(Nn * 8 + 255) / 256, 256>>>(gate, out);
}